// round 5
// baseline (speedup 1.0000x reference)
#include <cuda_runtime.h>

#define BATCH 8
#define DIM 256
#define SEQ 16384
#define KK 3
#define HID 85
#define OUTC (DIM*KK)
#define BN_EPS 1e-5f
#define FULLM 0xffffffffu

#define NCTA 256
#define NTHR 512
#define ROWS_PER_CTA 8          // 2048 rows / 256 CTAs
#define F4_PER_ROW (SEQ/4)      // 4096
#define F4_PER_THR (F4_PER_ROW/NTHR) // 8

// Scratch + barrier state (device globals — no allocation allowed)
__device__ float g_pooled[BATCH * DIM];
__device__ unsigned g_bar_count = 0;
__device__ unsigned g_bar_gen = 0;

__device__ __forceinline__ void grid_barrier() {
    __syncthreads();
    if (threadIdx.x == 0) {
        __threadfence();                                     // publish g_pooled
        unsigned my = *(volatile unsigned*)&g_bar_gen;
        unsigned a = atomicAdd(&g_bar_count, 1);
        if (a == NCTA - 1) {
            g_bar_count = 0;
            __threadfence();
            atomicAdd(&g_bar_gen, 1);
        } else {
            while (*(volatile unsigned*)&g_bar_gen == my) __nanosleep(64);
        }
        __threadfence();                                     // acquire
    }
    __syncthreads();
}

__global__ void __launch_bounds__(NTHR, 2)
fused_kernel(const float* __restrict__ x,
             const float* __restrict__ w1,
             const float* __restrict__ gamma,
             const float* __restrict__ beta,
             const float* __restrict__ mean,
             const float* __restrict__ var,
             const float* __restrict__ w2,
             const float* __restrict__ b2,
             const float* __restrict__ bias,
             float* __restrict__ out) {
    const int cta = blockIdx.x;
    const int tid = threadIdx.x;
    const int lane = tid & 31;
    const int row0 = cta * ROWS_PER_CTA;       // global row = b*DIM + c
    const int b = row0 / DIM;
    const int c0 = row0 % DIM;                 // 8 consecutive channels, same b

    __shared__ float sm[16];
    __shared__ float ys[HID];
    __shared__ float ws[ROWS_PER_CTA * KK];

    // ---------------- Phase 1: pool this CTA's 8 rows ----------------
    #pragma unroll 1
    for (int r = 0; r < ROWS_PER_CTA; r++) {
        const size_t rowoff = (size_t)(row0 + r) * SEQ;
        const float4* rp = (const float4*)(x + rowoff);

        float4 v[F4_PER_THR];
        #pragma unroll
        for (int j = 0; j < F4_PER_THR; j++)
            v[j] = rp[tid + j * NTHR];

        float s = 0.f;
        #pragma unroll
        for (int j = 0; j < F4_PER_THR; j++)
            s += (v[j].x + v[j].y) + (v[j].z + v[j].w);

        #pragma unroll
        for (int off = 16; off > 0; off >>= 1)
            s += __shfl_down_sync(FULLM, s, off);
        if (lane == 0) sm[tid >> 5] = s;
        __syncthreads();
        if (tid < 16) {
            float t = sm[tid];
            #pragma unroll
            for (int off = 8; off > 0; off >>= 1)
                t += __shfl_down_sync(0xffffu, t, off);
            if (tid == 0) g_pooled[row0 + r] = t * (1.f / SEQ);
        }
        __syncthreads();
    }

    // ---------------- Barrier: all pooled values published ----------------
    grid_barrier();

    // ---------------- Phase 2: y[b] (85) then w for our 8 channels --------
    if (tid < HID) {
        const float* wr = w1 + tid * DIM;
        const float* pp = g_pooled + b * DIM;
        float acc = 0.f;
        #pragma unroll 8
        for (int c = 0; c < DIM; c++) acc = fmaf(wr[c], __ldcg(pp + c), acc);
        float v = (acc - mean[tid]) * (gamma[tid] * rsqrtf(var[tid] + BN_EPS)) + beta[tid];
        ys[tid] = fmaxf(v, 0.f);
    }
    __syncthreads();
    if (tid < ROWS_PER_CTA * KK) {             // 24 outputs: o = (c0+j)*3+k
        const int o = c0 * KK + tid;
        const float* wr = w2 + o * HID;
        float acc = b2[o];
        #pragma unroll 5
        for (int h = 0; h < HID; h++) acc = fmaf(wr[h], ys[h], acc);
        ws[tid] = acc;
    }
    __syncthreads();

    // ---------------- Phase 3: conv same 8 rows, REVERSE order ------------
    #pragma unroll 1
    for (int r = ROWS_PER_CTA - 1; r >= 0; r--) {
        const int c = c0 + r;
        const size_t rowoff = (size_t)(row0 + r) * SEQ;
        const float w0  = ws[r * KK + 0];
        const float w1v = ws[r * KK + 1];
        const float w2v = ws[r * KK + 2];
        const float bb  = __ldg(bias + c);

        #pragma unroll 1
        for (int jj = F4_PER_THR - 1; jj >= 0; jj--) {   // reverse within row
            const int p = jj * NTHR + tid;               // f4 index
            const int t = p * 4;
            const float4 v = *(const float4*)(x + rowoff + t);

            float xl = __shfl_up_sync(FULLM, v.w, 1);
            float xr = __shfl_down_sync(FULLM, v.x, 1);
            if (lane == 0)
                xl = (t == 0) ? 0.f : __ldg(x + rowoff + t - 1);
            if (lane == 31)
                xr = (t + 4 >= SEQ) ? 0.f : __ldg(x + rowoff + t + 4);

            float4 o;
            o.x = fmaf(w0, xl,  fmaf(w1v, v.x, fmaf(w2v, v.y, bb)));
            o.y = fmaf(w0, v.x, fmaf(w1v, v.y, fmaf(w2v, v.z, bb)));
            o.z = fmaf(w0, v.y, fmaf(w1v, v.z, fmaf(w2v, v.w, bb)));
            o.w = fmaf(w0, v.z, fmaf(w1v, v.w, fmaf(w2v, xr,  bb)));

            __stcs((float4*)(out + rowoff + t), o);
        }
    }
}

// ---------------------------------------------------------------------------
// Launch. Inputs (metadata order): x, w1, bn_gamma, bn_beta, bn_mean, bn_var,
// w2, b2, bias. Output: fp32 [8, 256, 16384].
// ---------------------------------------------------------------------------
extern "C" void kernel_launch(void* const* d_in, const int* in_sizes, int n_in,
                              void* d_out, int out_size) {
    const float* x     = (const float*)d_in[0];
    const float* w1    = (const float*)d_in[1];
    const float* gamma = (const float*)d_in[2];
    const float* beta  = (const float*)d_in[3];
    const float* mean  = (const float*)d_in[4];
    const float* var   = (const float*)d_in[5];
    const float* w2    = (const float*)d_in[6];
    const float* b2    = (const float*)d_in[7];
    const float* bias  = (const float*)d_in[8];
    float* out = (float*)d_out;

    fused_kernel<<<NCTA, NTHR>>>(x, w1, gamma, beta, mean, var, w2, b2, bias, out);
}